// round 1
// baseline (speedup 1.0000x reference)
#include <cuda_runtime.h>
#include <cuda_bf16.h>
#include <cstdint>

#define NB      4
#define NSEQ    4096
#define DIM     512
#define BQ      64
#define BK      64
#define KSTRIDE 516   // fp32 K/V smem row stride (pad vs bank conflicts)
#define QSTRIDE 520   // bf16 Q smem row stride
#define PSTRIDE 65    // fp32 P smem row stride

#define SMEM_BYTES (BK*KSTRIDE*4 + BQ*QSTRIDE*2 + BQ*PSTRIDE*4)  // 215296 B

// ---- packed f32x2 helpers (FFMA2: 2x FFMA throughput, PTX-only path) ----
__device__ __forceinline__ unsigned long long pack2(float lo, float hi) {
    unsigned long long r;
    asm("mov.b64 %0, {%1, %2};" : "=l"(r) : "f"(lo), "f"(hi));
    return r;
}
__device__ __forceinline__ void unpack2(unsigned long long v, float& lo, float& hi) {
    asm("mov.b64 {%0, %1}, %2;" : "=f"(lo), "=f"(hi) : "l"(v));
}
__device__ __forceinline__ unsigned long long fma2(unsigned long long a,
                                                   unsigned long long b,
                                                   unsigned long long c) {
    unsigned long long d;
    asm("fma.rn.f32x2 %0, %1, %2, %3;" : "=l"(d) : "l"(a), "l"(b), "l"(c));
    return d;
}
__device__ __forceinline__ unsigned long long mul2(unsigned long long a,
                                                   unsigned long long b) {
    unsigned long long d;
    asm("mul.rn.f32x2 %0, %1, %2;" : "=l"(d) : "l"(a), "l"(b));
    return d;
}

// Flash-attention style: one CTA owns 64 query rows of one batch, streams
// 64-key tiles of X (acting as both K and V) through shared memory.
// Thread layout: 256 threads = 16 (ty: query groups) x 16 (tx: key/dim groups).
//   Score phase: thread (ty,tx) computes S[4q][4k], q = ty*4+qq, k = tx+16*kk.
//   PV phase:    thread (ty,tx) owns O[4q][32d], dims = tx*4 + 64*j + {0..3}.
extern "C" __global__ void __launch_bounds__(256, 1)
attn_fp32_kernel(const float* __restrict__ X, float* __restrict__ Y)
{
    extern __shared__ char smem[];
    float*          Ksm = (float*)smem;                                   // [BK][KSTRIDE] fp32 (K and V)
    __nv_bfloat16*  Qsm = (__nv_bfloat16*)(smem + BK * KSTRIDE * 4);      // [BQ][QSTRIDE] bf16
    float*          Psm = (float*)(smem + BK * KSTRIDE * 4 + BQ * QSTRIDE * 2); // [BQ][PSTRIDE]

    const int tid = threadIdx.x;
    const int tx  = tid & 15;
    const int ty  = tid >> 4;
    const int b   = blockIdx.x / (NSEQ / BQ);
    const int q0  = (blockIdx.x % (NSEQ / BQ)) * BQ;
    const float* __restrict__ Xb = X + (size_t)b * NSEQ * DIM;

    // ---- stage Q tile (bf16 is plenty for logits; softmax is ~one-hot) ----
    for (int i = tid; i < BQ * DIM; i += 256) {
        int r = i >> 9, c = i & 511;
        Qsm[r * QSTRIDE + c] = __float2bfloat16(Xb[(size_t)(q0 + r) * DIM + c]);
    }

    float m[4], l[4];
    unsigned long long O2[4][16];  // 4 q-rows x 16 f32x2 pairs = 32 dims/row
#pragma unroll
    for (int qq = 0; qq < 4; ++qq) {
        m[qq] = -1e30f;
        l[qq] = 0.0f;
#pragma unroll
        for (int jj = 0; jj < 16; ++jj) O2[qq][jj] = 0ull;
    }

    for (int kt = 0; kt < NSEQ / BK; ++kt) {
        __syncthreads();  // previous PV done with Ksm/Psm (also covers Q stage on iter 0)

        // ---- load K/V tile: 64x512 fp32, coalesced float4 ----
        const float* __restrict__ Ksrc = Xb + (size_t)kt * BK * DIM;
#pragma unroll
        for (int i = 0; i < (BK * DIM / 4) / 256; ++i) {
            int f4 = tid + i * 256;
            int r  = f4 >> 7;          // 128 float4 per row
            int c4 = f4 & 127;
            *(float4*)(Ksm + r * KSTRIDE + c4 * 4) =
                ((const float4*)(Ksrc + (size_t)r * DIM))[c4];
        }
        __syncthreads();

        // ---- scores: S[4][4] = Q[4 rows] . K[4 rows] over D=512 ----
        float s[4][4];
#pragma unroll
        for (int qq = 0; qq < 4; ++qq)
#pragma unroll
            for (int kk = 0; kk < 4; ++kk) s[qq][kk] = 0.0f;

#pragma unroll 2
        for (int d4 = 0; d4 < DIM / 4; ++d4) {
            float4 kv[4];
#pragma unroll
            for (int kk = 0; kk < 4; ++kk)
                kv[kk] = *(const float4*)(Ksm + (tx + 16 * kk) * KSTRIDE + d4 * 4);
#pragma unroll
            for (int qq = 0; qq < 4; ++qq) {
                const uint2 qp = ((const uint2*)(Qsm + (ty * 4 + qq) * QSTRIDE))[d4];
                float2 a  = __bfloat1622float2(*(const __nv_bfloat162*)&qp.x);
                float2 bb = __bfloat1622float2(*(const __nv_bfloat162*)&qp.y);
#pragma unroll
                for (int kk = 0; kk < 4; ++kk) {
                    s[qq][kk] += a.x * kv[kk].x;
                    s[qq][kk] += a.y * kv[kk].y;
                    s[qq][kk] += bb.x * kv[kk].z;
                    s[qq][kk] += bb.y * kv[kk].w;
                }
            }
        }

        // ---- online softmax update (16-lane row groups via shfl) ----
#pragma unroll
        for (int qq = 0; qq < 4; ++qq) {
            float tm = fmaxf(fmaxf(s[qq][0], s[qq][1]), fmaxf(s[qq][2], s[qq][3]));
#pragma unroll
            for (int o = 8; o > 0; o >>= 1)
                tm = fmaxf(tm, __shfl_xor_sync(0xffffffffu, tm, o));

            float mn    = fmaxf(m[qq], tm);
            float scale = __expf(m[qq] - mn);
            float p0 = __expf(s[qq][0] - mn);
            float p1 = __expf(s[qq][1] - mn);
            float p2 = __expf(s[qq][2] - mn);
            float p3 = __expf(s[qq][3] - mn);
            float rs = (p0 + p1) + (p2 + p3);
#pragma unroll
            for (int o = 8; o > 0; o >>= 1)
                rs += __shfl_xor_sync(0xffffffffu, rs, o);

            l[qq] = l[qq] * scale + rs;
            m[qq] = mn;

            unsigned long long sc2 = pack2(scale, scale);
#pragma unroll
            for (int jj = 0; jj < 16; ++jj) O2[qq][jj] = mul2(O2[qq][jj], sc2);

            const int qr = ty * 4 + qq;
            Psm[qr * PSTRIDE + tx]      = p0;
            Psm[qr * PSTRIDE + tx + 16] = p1;
            Psm[qr * PSTRIDE + tx + 32] = p2;
            Psm[qr * PSTRIDE + tx + 48] = p3;
        }
        __syncthreads();

        // ---- PV: O[4q][32d] += P[4q][64k] * V[64k][32d] (f32x2 packed) ----
#pragma unroll 2
        for (int k = 0; k < BK; ++k) {
            unsigned long long p2v[4];
#pragma unroll
            for (int qq = 0; qq < 4; ++qq) {
                float p = Psm[(ty * 4 + qq) * PSTRIDE + k];
                p2v[qq] = pack2(p, p);
            }
            const float* vrow = Ksm + k * KSTRIDE + tx * 4;
#pragma unroll
            for (int j = 0; j < 8; ++j) {
                unsigned long long v0 = *(const unsigned long long*)(vrow + j * 64);
                unsigned long long v1 = *(const unsigned long long*)(vrow + j * 64 + 2);
#pragma unroll
                for (int qq = 0; qq < 4; ++qq) {
                    O2[qq][2 * j]     = fma2(p2v[qq], v0, O2[qq][2 * j]);
                    O2[qq][2 * j + 1] = fma2(p2v[qq], v1, O2[qq][2 * j + 1]);
                }
            }
        }
    }

    // ---- epilogue: O /= l, write out ----
#pragma unroll
    for (int qq = 0; qq < 4; ++qq) {
        const float inv = 1.0f / l[qq];
        const int   qr  = ty * 4 + qq;
        float* out = Y + ((size_t)b * NSEQ + q0 + qr) * DIM + tx * 4;
#pragma unroll
        for (int j = 0; j < 8; ++j) {
            float x0, x1, x2, x3;
            unpack2(O2[qq][2 * j],     x0, x1);
            unpack2(O2[qq][2 * j + 1], x2, x3);
            float4 o;
            o.x = x0 * inv; o.y = x1 * inv; o.z = x2 * inv; o.w = x3 * inv;
            *(float4*)(out + j * 64) = o;
        }
    }
}

extern "C" void kernel_launch(void* const* d_in, const int* in_sizes, int n_in,
                              void* d_out, int out_size)
{
    const float* X = (const float*)d_in[0];
    float*       Y = (float*)d_out;
    cudaFuncSetAttribute(attn_fp32_kernel,
                         cudaFuncAttributeMaxDynamicSharedMemorySize, SMEM_BYTES);
    attn_fp32_kernel<<<NB * (NSEQ / BQ), 256, SMEM_BYTES>>>(X, Y);
}